// round 14
// baseline (speedup 1.0000x reference)
#include <cuda_runtime.h>
#include <cuda_fp16.h>
#include <mma.h>

using namespace nvcuda;

#define H      64
#define INF    128
#define NREL   8
#define NMAX   100000
#define EMAX   1600000

// ---- scratch ----
__device__ __align__(128) float   g_h  [NMAX * H];
__device__ __align__(128) __half2 g_hmh[NMAX * (H / 2)];  // hm in fp16 (gather payload)
__device__ __align__(128) float g_ps [NMAX];
__device__ __align__(128) float g_pd [NMAX];
__device__ __align__(128) float g_q  [NREL];
__device__ __align__(128) unsigned g_srcs[EMAX + 16];  // src | (typ<<20), dst-sorted (+pad)
__device__ __align__(128) float    g_cf  [EMAX + 16];  // 0.1*log(max(conf,1e-6)) (+pad)
__device__ __align__(128) int g_deg [NMAX];
__device__ __align__(128) int g_cur [NMAX];
__device__ __align__(128) int g_off [NMAX + 1];
__device__ __align__(128) int g_bsum[128];

#define LDA 72   // fp16 leading dim for A tiles (pad vs 64 to break conflicts)

// ---------------------------------------------------------------
// K0 (WMMA): h = relu(x @ W_in + b_in); also zeroes deg/cur slice.
// ---------------------------------------------------------------
__global__ __launch_bounds__(256) void k_input_mma(
    const float* __restrict__ x, const float* __restrict__ W,
    const float* __restrict__ b, int N)
{
    __shared__ __align__(128) char sm[32768];
    __half* As = (__half*)sm;               // [128][LDA]
    __half* Bs = (__half*)(sm + 18432);     // [64][64] row-major (k,n)
    float*  Cs = (float*)sm;                // [128][64]

    int t = threadIdx.x, w = t >> 5;
    int n0 = blockIdx.x * 128;

    if (t < 128 && n0 + t < N) { g_deg[n0 + t] = 0; g_cur[n0 + t] = 0; }

    wmma::fragment<wmma::accumulator, 16, 16, 16, float> acc[4];
    #pragma unroll
    for (int nt = 0; nt < 4; nt++) wmma::fill_fragment(acc[nt], 0.f);

    for (int p = 0; p < 2; p++) {
        __syncthreads();
        for (int i = t; i < 128 * 16; i += 256) {
            int r = i >> 4, c4 = i & 15;
            int node = n0 + r;
            float4 v = make_float4(0.f, 0.f, 0.f, 0.f);
            if (node < N) v = *(const float4*)&x[node * INF + p * 64 + c4 * 4];
            __half2 h0 = __floats2half2_rn(v.x, v.y);
            __half2 h1 = __floats2half2_rn(v.z, v.w);
            uint2 pk; pk.x = *(unsigned*)&h0; pk.y = *(unsigned*)&h1;
            *(uint2*)&As[r * LDA + c4 * 4] = pk;
        }
        for (int i = t; i < 64 * 16; i += 256) {
            int k = i >> 4, c4 = i & 15;
            float4 v = *(const float4*)&W[(p * 64 + k) * 64 + c4 * 4];
            __half2 h0 = __floats2half2_rn(v.x, v.y);
            __half2 h1 = __floats2half2_rn(v.z, v.w);
            uint2 pk; pk.x = *(unsigned*)&h0; pk.y = *(unsigned*)&h1;
            *(uint2*)&Bs[k * 64 + c4 * 4] = pk;
        }
        __syncthreads();
        #pragma unroll
        for (int ks = 0; ks < 4; ks++) {
            wmma::fragment<wmma::matrix_a, 16, 16, 16, __half, wmma::row_major> af;
            wmma::load_matrix_sync(af, As + (w * 16) * LDA + ks * 16, LDA);
            #pragma unroll
            for (int nt = 0; nt < 4; nt++) {
                wmma::fragment<wmma::matrix_b, 16, 16, 16, __half, wmma::row_major> bf;
                wmma::load_matrix_sync(bf, Bs + (ks * 16) * 64 + nt * 16, 64);
                wmma::mma_sync(acc[nt], af, bf, acc[nt]);
            }
        }
    }
    __syncthreads();
    #pragma unroll
    for (int nt = 0; nt < 4; nt++)
        wmma::store_matrix_sync(Cs + (w * 16) * 64 + nt * 16, acc[nt], 64,
                                wmma::mem_row_major);
    __syncthreads();
    for (int i = t; i < 128 * 16; i += 256) {
        int r = i >> 4, c4 = i & 15;
        int node = n0 + r;
        if (node < N) {
            float4 v = *(float4*)&Cs[r * 64 + c4 * 4];
            float4 bb = *(const float4*)&b[c4 * 4];
            float4 o;
            o.x = fmaxf(v.x + bb.x, 0.f);
            o.y = fmaxf(v.y + bb.y, 0.f);
            o.z = fmaxf(v.z + bb.z, 0.f);
            o.w = fmaxf(v.w + bb.w, 0.f);
            *(float4*)&g_h[node * H + c4 * 4] = o;
        }
    }
}

// ---------------------------------------------------------------
// K1 (WMMA): hm = h @ W_msg (fp16 out) + fused pd/ps + fused q (block 0).
// ---------------------------------------------------------------
__global__ __launch_bounds__(256) void k_msg_mma(
    const float* __restrict__ Wm, const float* __restrict__ att,
    const float* __restrict__ rel, const float* __restrict__ Wp, int N)
{
    __shared__ __align__(128) char sm[32768];
    __half* As = (__half*)sm;               // [128][LDA]
    __half* Bs = (__half*)(sm + 18432);     // [64][64]
    float*  Cs = (float*)sm;                // [128][64]

    int t = threadIdx.x, w = t >> 5, lane = t & 31;
    int n0 = blockIdx.x * 128;

    if (blockIdx.x == 0 && w < NREL) {
        float acc = 0.f;
        for (int hh = lane; hh < H; hh += 32) {
            float v = 0.f;
            #pragma unroll
            for (int r = 0; r < 16; r++) v += rel[w * 16 + r] * Wp[r * H + hh];
            acc += v * att[2 * H + hh];
        }
        #pragma unroll
        for (int o = 16; o; o >>= 1) acc += __shfl_xor_sync(0xffffffffu, acc, o);
        if (lane == 0) g_q[w] = acc;
    }

    for (int i = t; i < 128 * 16; i += 256) {
        int r = i >> 4, c4 = i & 15;
        int node = n0 + r;
        float4 v = make_float4(0.f, 0.f, 0.f, 0.f);
        if (node < N) v = *(const float4*)&g_h[node * H + c4 * 4];
        __half2 h0 = __floats2half2_rn(v.x, v.y);
        __half2 h1 = __floats2half2_rn(v.z, v.w);
        uint2 pk; pk.x = *(unsigned*)&h0; pk.y = *(unsigned*)&h1;
        *(uint2*)&As[r * LDA + c4 * 4] = pk;
    }
    for (int i = t; i < 64 * 16; i += 256) {
        int k = i >> 4, c4 = i & 15;
        float4 v = *(const float4*)&Wm[k * 64 + c4 * 4];
        __half2 h0 = __floats2half2_rn(v.x, v.y);
        __half2 h1 = __floats2half2_rn(v.z, v.w);
        uint2 pk; pk.x = *(unsigned*)&h0; pk.y = *(unsigned*)&h1;
        *(uint2*)&Bs[k * 64 + c4 * 4] = pk;
    }
    __syncthreads();

    wmma::fragment<wmma::accumulator, 16, 16, 16, float> acc[4];
    #pragma unroll
    for (int nt = 0; nt < 4; nt++) wmma::fill_fragment(acc[nt], 0.f);
    #pragma unroll
    for (int ks = 0; ks < 4; ks++) {
        wmma::fragment<wmma::matrix_a, 16, 16, 16, __half, wmma::row_major> af;
        wmma::load_matrix_sync(af, As + (w * 16) * LDA + ks * 16, LDA);
        #pragma unroll
        for (int nt = 0; nt < 4; nt++) {
            wmma::fragment<wmma::matrix_b, 16, 16, 16, __half, wmma::row_major> bf;
            wmma::load_matrix_sync(bf, Bs + (ks * 16) * 64 + nt * 16, 64);
            wmma::mma_sync(acc[nt], af, bf, acc[nt]);
        }
    }
    __syncthreads();
    #pragma unroll
    for (int nt = 0; nt < 4; nt++)
        wmma::store_matrix_sync(Cs + (w * 16) * 64 + nt * 16, acc[nt], 64,
                                wmma::mem_row_major);
    __syncthreads();

    float ad0 = att[lane],      ad1 = att[lane + 32];
    float as0 = att[64 + lane], as1 = att[96 + lane];
    for (int rr = 0; rr < 16; rr++) {
        int r = w * 16 + rr;
        int node = n0 + r;
        float v0 = Cs[r * 64 + lane];
        float v1 = Cs[r * 64 + 32 + lane];
        float pd = v0 * ad0 + v1 * ad1;
        float ps = v0 * as0 + v1 * as1;
        #pragma unroll
        for (int o = 16; o; o >>= 1) {
            pd += __shfl_xor_sync(0xffffffffu, pd, o);
            ps += __shfl_xor_sync(0xffffffffu, ps, o);
        }
        float u0 = Cs[r * 64 + 2 * lane];
        float u1 = Cs[r * 64 + 2 * lane + 1];
        if (node < N) {
            g_hmh[node * (H / 2) + lane] = __floats2half2_rn(u0, u1);
            if (lane == 0) { g_pd[node] = pd; g_ps[node] = ps; }
        }
    }
}

// ---------------------------------------------------------------
// Counting sort of edges by dst
// ---------------------------------------------------------------
__global__ __launch_bounds__(256) void k_hist(const int* __restrict__ dst, int E)
{
    int i = blockIdx.x * blockDim.x + threadIdx.x;
    if (i < E) atomicAdd(&g_deg[dst[i]], 1);
}

__global__ __launch_bounds__(1024) void k_scan1(int N)
{
    __shared__ int ws[32];
    int t = threadIdx.x, lane = t & 31, w = t >> 5;
    int i = blockIdx.x * 1024 + t;
    int v = (i < N) ? g_deg[i] : 0;
    #pragma unroll
    for (int o = 1; o < 32; o <<= 1) {
        int u = __shfl_up_sync(0xffffffffu, v, o);
        if (lane >= o) v += u;
    }
    if (lane == 31) ws[w] = v;
    __syncthreads();
    if (w == 0) {
        int bsum = ws[lane];
        #pragma unroll
        for (int o = 1; o < 32; o <<= 1) {
            int u = __shfl_up_sync(0xffffffffu, bsum, o);
            if (lane >= o) bsum += u;
        }
        ws[lane] = bsum;
    }
    __syncthreads();
    if (w) v += ws[w - 1];
    if (i < N) g_off[i + 1] = v;
    if (t == 1023) g_bsum[blockIdx.x] = v;
}

__global__ __launch_bounds__(1024) void k_scan23(int N, int nb)
{
    __shared__ int s[128];
    int t = threadIdx.x;
    if (t < 128) s[t] = (t < nb) ? g_bsum[t] : 0;
    __syncthreads();
    #pragma unroll
    for (int o = 1; o < 128; o <<= 1) {
        int v = (t >= o && t < 128) ? s[t - o] : 0;
        __syncthreads();
        if (t < 128) s[t] += v;
        __syncthreads();
    }
    int add = blockIdx.x ? s[blockIdx.x - 1] : 0;
    int i = blockIdx.x * 1024 + t;
    if (i < N) g_off[i + 1] += add;
    if (i == 0) g_off[0] = 0;
}

__global__ __launch_bounds__(256) void k_sortscatter(
    const int* __restrict__ src, const int* __restrict__ dst,
    const int* __restrict__ typ, const float* __restrict__ conf, int E)
{
    int i = blockIdx.x * blockDim.x + threadIdx.x;
    if (i >= E) return;
    int d = dst[i];
    int pos = g_off[d] + atomicAdd(&g_cur[d], 1);
    int t = min(max(typ[i], 0), NREL - 1);
    g_srcs[pos] = (unsigned)src[i] | ((unsigned)t << 20);
    g_cf[pos]   = 0.1f * __logf(fmaxf(conf[i], 1e-6f));
}

// ---------------------------------------------------------------
// K_aggr: warp-per-node; fused logit+exp (was k_w) + gather-sum +
// softmax normalization + residual + relu + layernorm.
// Depth-2 pipeline: meta prefetched 2 iters ahead, ps[src] 1 ahead.
// ---------------------------------------------------------------
__global__ __launch_bounds__(256) void k_aggr(
    const float* __restrict__ bias, const float* __restrict__ lng,
    const float* __restrict__ lnb, float* __restrict__ hout, int N)
{
    __shared__ float sq[NREL];
    if (threadIdx.x < NREL) sq[threadIdx.x] = g_q[threadIdx.x];
    __syncthreads();

    int n = (blockIdx.x * blockDim.x + threadIdx.x) >> 5;
    if (n >= N) return;
    int lane = threadIdx.x & 31;
    int half = lane >> 4;
    int l    = lane & 15;
    int beg = g_off[n], end = g_off[n + 1];
    float pdn = g_pd[n];
    float4 acc = make_float4(0.f, 0.f, 0.f, 0.f);
    float ssum = 0.f;

    int j = beg + half;
    // stage A (current, ps ready after prologue), stage B (meta ready)
    unsigned pA0 = 0, pA1 = 0;
    float cA0 = 0.f, cA1 = 0.f;
    if (j < end)     { pA0 = g_srcs[j];     cA0 = g_cf[j]; }
    if (j + 2 < end) { pA1 = g_srcs[j + 2]; cA1 = g_cf[j + 2]; }
    unsigned pB0 = g_srcs[j + 4], pB1 = g_srcs[j + 6];   // padded; safe
    float    cB0 = g_cf[j + 4],   cB1 = g_cf[j + 6];
    float sA0 = g_ps[pA0 & 0xFFFFF];
    float sA1 = g_ps[pA1 & 0xFFFFF];

    for (; j + 2 < end; j += 4) {
        // prefetch stage C meta (2 ahead) and stage B ps (1 ahead)
        unsigned pC0 = g_srcs[j + 8], pC1 = g_srcs[j + 10];
        float    cC0 = g_cf[j + 8],   cC1 = g_cf[j + 10];
        float sB0 = g_ps[pB0 & 0xFFFFF];
        float sB1 = g_ps[pB1 & 0xFFFFF];
        // logits + exp for stage A (identical arithmetic to old k_w)
        float e0 = pdn + sA0 + sq[pA0 >> 20];
        e0 = e0 > 0.f ? e0 : 0.2f * e0;
        e0 += cA0;
        float x0 = __expf(e0);
        float e1 = pdn + sA1 + sq[pA1 >> 20];
        e1 = e1 > 0.f ? e1 : 0.2f * e1;
        e1 += cA1;
        float x1 = __expf(e1);
        // gather hm rows for stage A
        uint2 r0 = *(const uint2*)&g_hmh[(pA0 & 0xFFFFF) * (H/2) + l * 2];
        uint2 r1 = *(const uint2*)&g_hmh[(pA1 & 0xFFFFF) * (H/2) + l * 2];
        float2 a0 = __half22float2(*(__half2*)&r0.x);
        float2 b0 = __half22float2(*(__half2*)&r0.y);
        float2 a1 = __half22float2(*(__half2*)&r1.x);
        float2 b1 = __half22float2(*(__half2*)&r1.y);
        acc.x += x0 * a0.x + x1 * a1.x;
        acc.y += x0 * a0.y + x1 * a1.y;
        acc.z += x0 * b0.x + x1 * b1.x;
        acc.w += x0 * b0.y + x1 * b1.y;
        ssum += x0 + x1;
        // rotate stages
        pA0 = pB0; pA1 = pB1; cA0 = cB0; cA1 = cB1; sA0 = sB0; sA1 = sB1;
        pB0 = pC0; pB1 = pC1; cB0 = cC0; cB1 = cC1;
    }
    if (j < end) {
        float e0 = pdn + sA0 + sq[pA0 >> 20];
        e0 = e0 > 0.f ? e0 : 0.2f * e0;
        e0 += cA0;
        float x0 = __expf(e0);
        uint2 r = *(const uint2*)&g_hmh[(pA0 & 0xFFFFF) * (H/2) + l * 2];
        float2 a = __half22float2(*(__half2*)&r.x);
        float2 b = __half22float2(*(__half2*)&r.y);
        acc.x += x0 * a.x; acc.y += x0 * a.y;
        acc.z += x0 * b.x; acc.w += x0 * b.y;
        ssum += x0;
    }

    acc.x += __shfl_xor_sync(0xffffffffu, acc.x, 16);
    acc.y += __shfl_xor_sync(0xffffffffu, acc.y, 16);
    acc.z += __shfl_xor_sync(0xffffffffu, acc.z, 16);
    acc.w += __shfl_xor_sync(0xffffffffu, acc.w, 16);
    ssum  += __shfl_xor_sync(0xffffffffu, ssum,  16);
    float inv = (ssum > 0.f) ? (1.f / ssum) : 0.f;
    float4 hv = *(const float4*)&g_h[n * H + l * 4];
    float4 bb = *(const float4*)&bias[l * 4];
    float4 u;
    u.x = hv.x + fmaxf(acc.x * inv + bb.x, 0.f);
    u.y = hv.y + fmaxf(acc.y * inv + bb.y, 0.f);
    u.z = hv.z + fmaxf(acc.z * inv + bb.z, 0.f);
    u.w = hv.w + fmaxf(acc.w * inv + bb.w, 0.f);
    float s = u.x + u.y + u.z + u.w;
    #pragma unroll
    for (int o = 16; o; o >>= 1) s += __shfl_xor_sync(0xffffffffu, s, o);
    float mu = s * (1.f / 128.f);
    float4 d4 = make_float4(u.x - mu, u.y - mu, u.z - mu, u.w - mu);
    float vs = d4.x*d4.x + d4.y*d4.y + d4.z*d4.z + d4.w*d4.w;
    #pragma unroll
    for (int o = 16; o; o >>= 1) vs += __shfl_xor_sync(0xffffffffu, vs, o);
    float invs = rsqrtf(vs * (1.f / 128.f) + 1e-5f);
    if (half == 0) {
        float4 g4 = *(const float4*)&lng[l * 4];
        float4 b2 = *(const float4*)&lnb[l * 4];
        float* outp = hout ? hout : g_h;
        float4 o4;
        o4.x = d4.x * invs * g4.x + b2.x;
        o4.y = d4.y * invs * g4.y + b2.y;
        o4.z = d4.z * invs * g4.z + b2.z;
        o4.w = d4.w * invs * g4.w + b2.w;
        *(float4*)&outp[n * H + l * 4] = o4;
    }
}

// ---------------------------------------------------------------
extern "C" void kernel_launch(void* const* d_in, const int* in_sizes, int n_in,
                              void* d_out, int out_size)
{
    const float* x         = (const float*)d_in[0];
    const float* W_in      = (const float*)d_in[1];
    const float* b_in      = (const float*)d_in[2];
    const float* W_msg     = (const float*)d_in[3];
    const float* rel_emb   = (const float*)d_in[4];
    const float* W_relproj = (const float*)d_in[5];
    const float* att_vec   = (const float*)d_in[6];
    const float* bias      = (const float*)d_in[7];
    const float* ln_g      = (const float*)d_in[8];
    const float* ln_b      = (const float*)d_in[9];
    const float* edge_attr = (const float*)d_in[10];
    const int*   edge_index= (const int*)d_in[11];
    const int*   edge_type = (const int*)d_in[12];
    float* out = (float*)d_out;

    int N = in_sizes[0] / INF;
    int E = in_sizes[12];
    int L = in_sizes[7] / H;
    const int* src = edge_index;
    const int* dst = edge_index + E;
    int nb = (N + 1023) / 1024;

    k_input_mma<<<(N + 127) / 128, 256>>>(x, W_in, b_in, N);   // + zeroes deg/cur

    k_hist<<<(E + 255) / 256, 256>>>(dst, E);
    k_scan1<<<nb, 1024>>>(N);
    k_scan23<<<nb, 1024>>>(N, nb);
    k_sortscatter<<<(E + 255) / 256, 256>>>(src, dst, edge_type, edge_attr, E);

    for (int l = 0; l < L; l++) {
        k_msg_mma<<<(N + 127) / 128, 256>>>(W_msg + l * H * H,
                                            att_vec + l * 3 * H,
                                            rel_emb + l * NREL * 16,
                                            W_relproj + l * 16 * H, N);
        k_aggr<<<(N * 32 + 255) / 256, 256>>>(bias + l * H,
                                              ln_g + l * H, ln_b + l * H,
                                              (l == L - 1) ? out : (float*)nullptr,
                                              N);
    }
}

// round 15
// speedup vs baseline: 1.0775x; 1.0775x over previous
#include <cuda_runtime.h>
#include <cuda_fp16.h>
#include <mma.h>

using namespace nvcuda;

#define H      64
#define INF    128
#define NREL   8
#define NMAX   100000
#define EMAX   1600000

// ---- scratch ----
__device__ __align__(128) float   g_h  [NMAX * H];
__device__ __align__(128) __half2 g_hmh[NMAX * (H / 2)];  // hm in fp16 (gather payload)
__device__ __align__(128) float g_ps [NMAX];
__device__ __align__(128) float g_pd [NMAX];
__device__ __align__(128) float g_q  [NREL];
__device__ __align__(128) unsigned g_srcs[EMAX + 8];   // src | (typ<<20), dst-sorted
__device__ __align__(128) int      g_dsts[EMAX];
__device__ __align__(128) float    g_cf  [EMAX];
__device__ __align__(128) float    g_ex  [EMAX + 8];   // exp(e) (+pad for prefetch)
__device__ __align__(128) int g_deg [NMAX];
__device__ __align__(128) int g_cur [NMAX];
__device__ __align__(128) int g_off [NMAX + 1];
__device__ __align__(128) int g_bsum[128];

#define LDA 72   // fp16 leading dim for A tiles (pad vs 64 to break conflicts)

// ---------------------------------------------------------------
// K0 (WMMA): h = relu(x @ W_in + b_in); also zeroes deg/cur slice.
// ---------------------------------------------------------------
__global__ __launch_bounds__(256) void k_input_mma(
    const float* __restrict__ x, const float* __restrict__ W,
    const float* __restrict__ b, int N)
{
    __shared__ __align__(128) char sm[32768];
    __half* As = (__half*)sm;               // [128][LDA]
    __half* Bs = (__half*)(sm + 18432);     // [64][64] row-major (k,n)
    float*  Cs = (float*)sm;                // [128][64]

    int t = threadIdx.x, w = t >> 5;
    int n0 = blockIdx.x * 128;

    if (t < 128 && n0 + t < N) { g_deg[n0 + t] = 0; g_cur[n0 + t] = 0; }

    wmma::fragment<wmma::accumulator, 16, 16, 16, float> acc[4];
    #pragma unroll
    for (int nt = 0; nt < 4; nt++) wmma::fill_fragment(acc[nt], 0.f);

    for (int p = 0; p < 2; p++) {
        __syncthreads();
        for (int i = t; i < 128 * 16; i += 256) {
            int r = i >> 4, c4 = i & 15;
            int node = n0 + r;
            float4 v = make_float4(0.f, 0.f, 0.f, 0.f);
            if (node < N) v = *(const float4*)&x[node * INF + p * 64 + c4 * 4];
            __half2 h0 = __floats2half2_rn(v.x, v.y);
            __half2 h1 = __floats2half2_rn(v.z, v.w);
            uint2 pk; pk.x = *(unsigned*)&h0; pk.y = *(unsigned*)&h1;
            *(uint2*)&As[r * LDA + c4 * 4] = pk;
        }
        for (int i = t; i < 64 * 16; i += 256) {
            int k = i >> 4, c4 = i & 15;
            float4 v = *(const float4*)&W[(p * 64 + k) * 64 + c4 * 4];
            __half2 h0 = __floats2half2_rn(v.x, v.y);
            __half2 h1 = __floats2half2_rn(v.z, v.w);
            uint2 pk; pk.x = *(unsigned*)&h0; pk.y = *(unsigned*)&h1;
            *(uint2*)&Bs[k * 64 + c4 * 4] = pk;
        }
        __syncthreads();
        #pragma unroll
        for (int ks = 0; ks < 4; ks++) {
            wmma::fragment<wmma::matrix_a, 16, 16, 16, __half, wmma::row_major> af;
            wmma::load_matrix_sync(af, As + (w * 16) * LDA + ks * 16, LDA);
            #pragma unroll
            for (int nt = 0; nt < 4; nt++) {
                wmma::fragment<wmma::matrix_b, 16, 16, 16, __half, wmma::row_major> bf;
                wmma::load_matrix_sync(bf, Bs + (ks * 16) * 64 + nt * 16, 64);
                wmma::mma_sync(acc[nt], af, bf, acc[nt]);
            }
        }
    }
    __syncthreads();
    #pragma unroll
    for (int nt = 0; nt < 4; nt++)
        wmma::store_matrix_sync(Cs + (w * 16) * 64 + nt * 16, acc[nt], 64,
                                wmma::mem_row_major);
    __syncthreads();
    for (int i = t; i < 128 * 16; i += 256) {
        int r = i >> 4, c4 = i & 15;
        int node = n0 + r;
        if (node < N) {
            float4 v = *(float4*)&Cs[r * 64 + c4 * 4];
            float4 bb = *(const float4*)&b[c4 * 4];
            float4 o;
            o.x = fmaxf(v.x + bb.x, 0.f);
            o.y = fmaxf(v.y + bb.y, 0.f);
            o.z = fmaxf(v.z + bb.z, 0.f);
            o.w = fmaxf(v.w + bb.w, 0.f);
            *(float4*)&g_h[node * H + c4 * 4] = o;
        }
    }
}

// ---------------------------------------------------------------
// K1 (WMMA): hm = h @ W_msg (fp16 out) + fused pd/ps + fused q (block 0).
// ---------------------------------------------------------------
__global__ __launch_bounds__(256) void k_msg_mma(
    const float* __restrict__ Wm, const float* __restrict__ att,
    const float* __restrict__ rel, const float* __restrict__ Wp, int N)
{
    __shared__ __align__(128) char sm[32768];
    __half* As = (__half*)sm;               // [128][LDA]
    __half* Bs = (__half*)(sm + 18432);     // [64][64]
    float*  Cs = (float*)sm;                // [128][64]

    int t = threadIdx.x, w = t >> 5, lane = t & 31;
    int n0 = blockIdx.x * 128;

    if (blockIdx.x == 0 && w < NREL) {
        float acc = 0.f;
        for (int hh = lane; hh < H; hh += 32) {
            float v = 0.f;
            #pragma unroll
            for (int r = 0; r < 16; r++) v += rel[w * 16 + r] * Wp[r * H + hh];
            acc += v * att[2 * H + hh];
        }
        #pragma unroll
        for (int o = 16; o; o >>= 1) acc += __shfl_xor_sync(0xffffffffu, acc, o);
        if (lane == 0) g_q[w] = acc;
    }

    for (int i = t; i < 128 * 16; i += 256) {
        int r = i >> 4, c4 = i & 15;
        int node = n0 + r;
        float4 v = make_float4(0.f, 0.f, 0.f, 0.f);
        if (node < N) v = *(const float4*)&g_h[node * H + c4 * 4];
        __half2 h0 = __floats2half2_rn(v.x, v.y);
        __half2 h1 = __floats2half2_rn(v.z, v.w);
        uint2 pk; pk.x = *(unsigned*)&h0; pk.y = *(unsigned*)&h1;
        *(uint2*)&As[r * LDA + c4 * 4] = pk;
    }
    for (int i = t; i < 64 * 16; i += 256) {
        int k = i >> 4, c4 = i & 15;
        float4 v = *(const float4*)&Wm[k * 64 + c4 * 4];
        __half2 h0 = __floats2half2_rn(v.x, v.y);
        __half2 h1 = __floats2half2_rn(v.z, v.w);
        uint2 pk; pk.x = *(unsigned*)&h0; pk.y = *(unsigned*)&h1;
        *(uint2*)&Bs[k * 64 + c4 * 4] = pk;
    }
    __syncthreads();

    wmma::fragment<wmma::accumulator, 16, 16, 16, float> acc[4];
    #pragma unroll
    for (int nt = 0; nt < 4; nt++) wmma::fill_fragment(acc[nt], 0.f);
    #pragma unroll
    for (int ks = 0; ks < 4; ks++) {
        wmma::fragment<wmma::matrix_a, 16, 16, 16, __half, wmma::row_major> af;
        wmma::load_matrix_sync(af, As + (w * 16) * LDA + ks * 16, LDA);
        #pragma unroll
        for (int nt = 0; nt < 4; nt++) {
            wmma::fragment<wmma::matrix_b, 16, 16, 16, __half, wmma::row_major> bf;
            wmma::load_matrix_sync(bf, Bs + (ks * 16) * 64 + nt * 16, 64);
            wmma::mma_sync(acc[nt], af, bf, acc[nt]);
        }
    }
    __syncthreads();
    #pragma unroll
    for (int nt = 0; nt < 4; nt++)
        wmma::store_matrix_sync(Cs + (w * 16) * 64 + nt * 16, acc[nt], 64,
                                wmma::mem_row_major);
    __syncthreads();

    float ad0 = att[lane],      ad1 = att[lane + 32];
    float as0 = att[64 + lane], as1 = att[96 + lane];
    for (int rr = 0; rr < 16; rr++) {
        int r = w * 16 + rr;
        int node = n0 + r;
        float v0 = Cs[r * 64 + lane];
        float v1 = Cs[r * 64 + 32 + lane];
        float pd = v0 * ad0 + v1 * ad1;
        float ps = v0 * as0 + v1 * as1;
        #pragma unroll
        for (int o = 16; o; o >>= 1) {
            pd += __shfl_xor_sync(0xffffffffu, pd, o);
            ps += __shfl_xor_sync(0xffffffffu, ps, o);
        }
        float u0 = Cs[r * 64 + 2 * lane];
        float u1 = Cs[r * 64 + 2 * lane + 1];
        if (node < N) {
            g_hmh[node * (H / 2) + lane] = __floats2half2_rn(u0, u1);
            if (lane == 0) { g_pd[node] = pd; g_ps[node] = ps; }
        }
    }
}

// ---------------------------------------------------------------
// Counting sort of edges by dst
// ---------------------------------------------------------------
__global__ __launch_bounds__(256) void k_hist(const int* __restrict__ dst, int E)
{
    int i = blockIdx.x * blockDim.x + threadIdx.x;
    if (i < E) atomicAdd(&g_deg[dst[i]], 1);
}

__global__ __launch_bounds__(1024) void k_scan1(int N)
{
    __shared__ int ws[32];
    int t = threadIdx.x, lane = t & 31, w = t >> 5;
    int i = blockIdx.x * 1024 + t;
    int v = (i < N) ? g_deg[i] : 0;
    #pragma unroll
    for (int o = 1; o < 32; o <<= 1) {
        int u = __shfl_up_sync(0xffffffffu, v, o);
        if (lane >= o) v += u;
    }
    if (lane == 31) ws[w] = v;
    __syncthreads();
    if (w == 0) {
        int bsum = ws[lane];
        #pragma unroll
        for (int o = 1; o < 32; o <<= 1) {
            int u = __shfl_up_sync(0xffffffffu, bsum, o);
            if (lane >= o) bsum += u;
        }
        ws[lane] = bsum;
    }
    __syncthreads();
    if (w) v += ws[w - 1];
    if (i < N) g_off[i + 1] = v;
    if (t == 1023) g_bsum[blockIdx.x] = v;
}

__global__ __launch_bounds__(1024) void k_scan23(int N, int nb)
{
    __shared__ int s[128];
    int t = threadIdx.x;
    if (t < 128) s[t] = (t < nb) ? g_bsum[t] : 0;
    __syncthreads();
    #pragma unroll
    for (int o = 1; o < 128; o <<= 1) {
        int v = (t >= o && t < 128) ? s[t - o] : 0;
        __syncthreads();
        if (t < 128) s[t] += v;
        __syncthreads();
    }
    int add = blockIdx.x ? s[blockIdx.x - 1] : 0;
    int i = blockIdx.x * 1024 + t;
    if (i < N) g_off[i + 1] += add;
    if (i == 0) g_off[0] = 0;
}

__global__ __launch_bounds__(256) void k_sortscatter(
    const int* __restrict__ src, const int* __restrict__ dst,
    const int* __restrict__ typ, const float* __restrict__ conf, int E)
{
    int i = blockIdx.x * blockDim.x + threadIdx.x;
    if (i >= E) return;
    int d = dst[i];
    int pos = g_off[d] + atomicAdd(&g_cur[d], 1);
    int t = min(max(typ[i], 0), NREL - 1);
    g_srcs[pos] = (unsigned)src[i] | ((unsigned)t << 20);
    g_dsts[pos] = d;
    g_cf[pos]   = 0.1f * __logf(fmaxf(conf[i], 1e-6f));
}

// ---------------------------------------------------------------
// K_w: edge-parallel coalesced logit + exp, 2 edges per thread
// (vectorized loads/stores; arithmetic identical to R9)
// ---------------------------------------------------------------
__global__ __launch_bounds__(256) void k_w(int E)
{
    int i = (blockIdx.x * blockDim.x + threadIdx.x) * 2;
    if (i >= E) return;
    uint2  p2 = *(const uint2*)&g_srcs[i];
    int2   d2 = *(const int2*)&g_dsts[i];
    float2 c2 = *(const float2*)&g_cf[i];
    float e0 = g_pd[d2.x] + g_ps[p2.x & 0xFFFFF] + g_q[p2.x >> 20];
    e0 = e0 > 0.f ? e0 : 0.2f * e0;
    e0 += c2.x;
    float e1 = g_pd[d2.y] + g_ps[p2.y & 0xFFFFF] + g_q[p2.y >> 20];
    e1 = e1 > 0.f ? e1 : 0.2f * e1;
    e1 += c2.y;
    if (i + 1 < E) {
        *(float2*)&g_ex[i] = make_float2(__expf(e0), __expf(e1));
    } else {
        g_ex[i] = __expf(e0);
    }
}

// ---------------------------------------------------------------
// K_aggr: warp-per-node gather-sum (fp16 payload), software-pipelined
// metadata prefetch, fused softmax-normalize + residual + relu + LN.
// (exact R9 form)
// ---------------------------------------------------------------
__global__ __launch_bounds__(256) void k_aggr(
    const float* __restrict__ bias, const float* __restrict__ lng,
    const float* __restrict__ lnb, float* __restrict__ hout, int N)
{
    int n = (blockIdx.x * blockDim.x + threadIdx.x) >> 5;
    if (n >= N) return;
    int lane = threadIdx.x & 31;
    int half = lane >> 4;
    int l    = lane & 15;
    int beg = g_off[n], end = g_off[n + 1];
    float4 acc = make_float4(0.f, 0.f, 0.f, 0.f);
    float ssum = 0.f;

    int j = beg + half;
    unsigned p0 = 0, p1 = 0;
    float e0 = 0.f, e1 = 0.f;
    if (j < end)     { p0 = g_srcs[j];     e0 = g_ex[j]; }
    if (j + 2 < end) { p1 = g_srcs[j + 2]; e1 = g_ex[j + 2]; }
    for (; j + 2 < end; j += 4) {
        // prefetch next pair's metadata (padded arrays make OOB reads safe;
        // values only consumed if the next iteration's guard holds)
        unsigned q0 = g_srcs[j + 4], q1 = g_srcs[j + 6];
        float f0 = g_ex[j + 4], f1 = g_ex[j + 6];
        uint2 r0 = *(const uint2*)&g_hmh[(p0 & 0xFFFFF) * (H/2) + l * 2];
        uint2 r1 = *(const uint2*)&g_hmh[(p1 & 0xFFFFF) * (H/2) + l * 2];
        float2 a0 = __half22float2(*(__half2*)&r0.x);
        float2 b0 = __half22float2(*(__half2*)&r0.y);
        float2 a1 = __half22float2(*(__half2*)&r1.x);
        float2 b1 = __half22float2(*(__half2*)&r1.y);
        acc.x += e0 * a0.x + e1 * a1.x;
        acc.y += e0 * a0.y + e1 * a1.y;
        acc.z += e0 * b0.x + e1 * b1.x;
        acc.w += e0 * b0.y + e1 * b1.y;
        ssum += e0 + e1;
        p0 = q0; p1 = q1; e0 = f0; e1 = f1;
    }
    if (j < end) {
        uint2 r = *(const uint2*)&g_hmh[(p0 & 0xFFFFF) * (H/2) + l * 2];
        float2 a = __half22float2(*(__half2*)&r.x);
        float2 b = __half22float2(*(__half2*)&r.y);
        acc.x += e0 * a.x; acc.y += e0 * a.y;
        acc.z += e0 * b.x; acc.w += e0 * b.y;
        ssum += e0;
    }

    acc.x += __shfl_xor_sync(0xffffffffu, acc.x, 16);
    acc.y += __shfl_xor_sync(0xffffffffu, acc.y, 16);
    acc.z += __shfl_xor_sync(0xffffffffu, acc.z, 16);
    acc.w += __shfl_xor_sync(0xffffffffu, acc.w, 16);
    ssum  += __shfl_xor_sync(0xffffffffu, ssum,  16);
    float inv = (ssum > 0.f) ? (1.f / ssum) : 0.f;
    float4 hv = *(const float4*)&g_h[n * H + l * 4];
    float4 bb = *(const float4*)&bias[l * 4];
    float4 u;
    u.x = hv.x + fmaxf(acc.x * inv + bb.x, 0.f);
    u.y = hv.y + fmaxf(acc.y * inv + bb.y, 0.f);
    u.z = hv.z + fmaxf(acc.z * inv + bb.z, 0.f);
    u.w = hv.w + fmaxf(acc.w * inv + bb.w, 0.f);
    float s = u.x + u.y + u.z + u.w;
    #pragma unroll
    for (int o = 16; o; o >>= 1) s += __shfl_xor_sync(0xffffffffu, s, o);
    float mu = s * (1.f / 128.f);
    float4 d4 = make_float4(u.x - mu, u.y - mu, u.z - mu, u.w - mu);
    float vs = d4.x*d4.x + d4.y*d4.y + d4.z*d4.z + d4.w*d4.w;
    #pragma unroll
    for (int o = 16; o; o >>= 1) vs += __shfl_xor_sync(0xffffffffu, vs, o);
    float invs = rsqrtf(vs * (1.f / 128.f) + 1e-5f);
    if (half == 0) {
        float4 g4 = *(const float4*)&lng[l * 4];
        float4 b2 = *(const float4*)&lnb[l * 4];
        float* outp = hout ? hout : g_h;
        float4 o4;
        o4.x = d4.x * invs * g4.x + b2.x;
        o4.y = d4.y * invs * g4.y + b2.y;
        o4.z = d4.z * invs * g4.z + b2.z;
        o4.w = d4.w * invs * g4.w + b2.w;
        *(float4*)&outp[n * H + l * 4] = o4;
    }
}

// ---------------------------------------------------------------
extern "C" void kernel_launch(void* const* d_in, const int* in_sizes, int n_in,
                              void* d_out, int out_size)
{
    const float* x         = (const float*)d_in[0];
    const float* W_in      = (const float*)d_in[1];
    const float* b_in      = (const float*)d_in[2];
    const float* W_msg     = (const float*)d_in[3];
    const float* rel_emb   = (const float*)d_in[4];
    const float* W_relproj = (const float*)d_in[5];
    const float* att_vec   = (const float*)d_in[6];
    const float* bias      = (const float*)d_in[7];
    const float* ln_g      = (const float*)d_in[8];
    const float* ln_b      = (const float*)d_in[9];
    const float* edge_attr = (const float*)d_in[10];
    const int*   edge_index= (const int*)d_in[11];
    const int*   edge_type = (const int*)d_in[12];
    float* out = (float*)d_out;

    int N = in_sizes[0] / INF;
    int E = in_sizes[12];
    int L = in_sizes[7] / H;
    const int* src = edge_index;
    const int* dst = edge_index + E;
    int nb = (N + 1023) / 1024;

    k_input_mma<<<(N + 127) / 128, 256>>>(x, W_in, b_in, N);   // + zeroes deg/cur

    k_hist<<<(E + 255) / 256, 256>>>(dst, E);
    k_scan1<<<nb, 1024>>>(N);
    k_scan23<<<nb, 1024>>>(N, nb);
    k_sortscatter<<<(E + 255) / 256, 256>>>(src, dst, edge_type, edge_attr, E);

    for (int l = 0; l < L; l++) {
        k_msg_mma<<<(N + 127) / 128, 256>>>(W_msg + l * H * H,
                                            att_vec + l * 3 * H,
                                            rel_emb + l * NREL * 16,
                                            W_relproj + l * 16 * H, N);
        k_w<<<(E / 2 + 255) / 256, 256>>>(E);
        k_aggr<<<(N * 32 + 255) / 256, 256>>>(bias + l * H,
                                              ln_g + l * H, ln_b + l * H,
                                              (l == L - 1) ? out : (float*)nullptr,
                                              N);
    }
}

// round 16
// speedup vs baseline: 1.0862x; 1.0081x over previous
#include <cuda_runtime.h>
#include <cuda_fp16.h>
#include <mma.h>

using namespace nvcuda;

#define H      64
#define INF    128
#define NREL   8
#define NMAX   100000
#define EMAX   1600000

// ---- scratch ----
__device__ __align__(128) float   g_h  [NMAX * H];
__device__ __align__(128) __half2 g_hmh[NMAX * (H / 2)];  // hm in fp16 (gather payload)
__device__ __align__(128) float g_ps [NMAX];
__device__ __align__(128) float g_pd [NMAX];
__device__ __align__(128) float g_q  [NREL];
__device__ __align__(128) unsigned g_srcs[EMAX + 8];   // src | (typ<<20), dst-sorted
__device__ __align__(128) int      g_dsts[EMAX];
__device__ __align__(128) float    g_cf  [EMAX];
__device__ __align__(128) float    g_ex  [EMAX + 8];   // exp(e) (+pad for prefetch)
__device__ __align__(128) int g_deg [NMAX];
__device__ __align__(128) int g_cur [NMAX];
__device__ __align__(128) int g_off [NMAX + 1];
__device__ __align__(128) int g_bsum[128];

#define LDA 72   // fp16 leading dim for A tiles (pad vs 64 to break conflicts)

// ---------------------------------------------------------------
// K0 (WMMA): h = relu(x @ W_in + b_in); also zeroes deg/cur slice.
// ---------------------------------------------------------------
__global__ __launch_bounds__(256) void k_input_mma(
    const float* __restrict__ x, const float* __restrict__ W,
    const float* __restrict__ b, int N)
{
    __shared__ __align__(128) char sm[32768];
    __half* As = (__half*)sm;               // [128][LDA]
    __half* Bs = (__half*)(sm + 18432);     // [64][64] row-major (k,n)
    float*  Cs = (float*)sm;                // [128][64]

    int t = threadIdx.x, w = t >> 5;
    int n0 = blockIdx.x * 128;

    cudaGridDependencySynchronize();

    if (t < 128 && n0 + t < N) { g_deg[n0 + t] = 0; g_cur[n0 + t] = 0; }

    wmma::fragment<wmma::accumulator, 16, 16, 16, float> acc[4];
    #pragma unroll
    for (int nt = 0; nt < 4; nt++) wmma::fill_fragment(acc[nt], 0.f);

    for (int p = 0; p < 2; p++) {
        __syncthreads();
        for (int i = t; i < 128 * 16; i += 256) {
            int r = i >> 4, c4 = i & 15;
            int node = n0 + r;
            float4 v = make_float4(0.f, 0.f, 0.f, 0.f);
            if (node < N) v = *(const float4*)&x[node * INF + p * 64 + c4 * 4];
            __half2 h0 = __floats2half2_rn(v.x, v.y);
            __half2 h1 = __floats2half2_rn(v.z, v.w);
            uint2 pk; pk.x = *(unsigned*)&h0; pk.y = *(unsigned*)&h1;
            *(uint2*)&As[r * LDA + c4 * 4] = pk;
        }
        for (int i = t; i < 64 * 16; i += 256) {
            int k = i >> 4, c4 = i & 15;
            float4 v = *(const float4*)&W[(p * 64 + k) * 64 + c4 * 4];
            __half2 h0 = __floats2half2_rn(v.x, v.y);
            __half2 h1 = __floats2half2_rn(v.z, v.w);
            uint2 pk; pk.x = *(unsigned*)&h0; pk.y = *(unsigned*)&h1;
            *(uint2*)&Bs[k * 64 + c4 * 4] = pk;
        }
        __syncthreads();
        #pragma unroll
        for (int ks = 0; ks < 4; ks++) {
            wmma::fragment<wmma::matrix_a, 16, 16, 16, __half, wmma::row_major> af;
            wmma::load_matrix_sync(af, As + (w * 16) * LDA + ks * 16, LDA);
            #pragma unroll
            for (int nt = 0; nt < 4; nt++) {
                wmma::fragment<wmma::matrix_b, 16, 16, 16, __half, wmma::row_major> bf;
                wmma::load_matrix_sync(bf, Bs + (ks * 16) * 64 + nt * 16, 64);
                wmma::mma_sync(acc[nt], af, bf, acc[nt]);
            }
        }
    }
    __syncthreads();
    #pragma unroll
    for (int nt = 0; nt < 4; nt++)
        wmma::store_matrix_sync(Cs + (w * 16) * 64 + nt * 16, acc[nt], 64,
                                wmma::mem_row_major);
    __syncthreads();
    for (int i = t; i < 128 * 16; i += 256) {
        int r = i >> 4, c4 = i & 15;
        int node = n0 + r;
        if (node < N) {
            float4 v = *(float4*)&Cs[r * 64 + c4 * 4];
            float4 bb = *(const float4*)&b[c4 * 4];
            float4 o;
            o.x = fmaxf(v.x + bb.x, 0.f);
            o.y = fmaxf(v.y + bb.y, 0.f);
            o.z = fmaxf(v.z + bb.z, 0.f);
            o.w = fmaxf(v.w + bb.w, 0.f);
            *(float4*)&g_h[node * H + c4 * 4] = o;
        }
    }
}

// ---------------------------------------------------------------
// K1 (WMMA): hm = h @ W_msg (fp16 out) + fused pd/ps + fused q (block 0).
// ---------------------------------------------------------------
__global__ __launch_bounds__(256) void k_msg_mma(
    const float* __restrict__ Wm, const float* __restrict__ att,
    const float* __restrict__ rel, const float* __restrict__ Wp, int N)
{
    __shared__ __align__(128) char sm[32768];
    __half* As = (__half*)sm;               // [128][LDA]
    __half* Bs = (__half*)(sm + 18432);     // [64][64]
    float*  Cs = (float*)sm;                // [128][64]

    int t = threadIdx.x, w = t >> 5, lane = t & 31;
    int n0 = blockIdx.x * 128;

    // weights/att are kernel inputs (not predecessor-written): stage B early
    for (int i = t; i < 64 * 16; i += 256) {
        int k = i >> 4, c4 = i & 15;
        float4 v = *(const float4*)&Wm[k * 64 + c4 * 4];
        __half2 h0 = __floats2half2_rn(v.x, v.y);
        __half2 h1 = __floats2half2_rn(v.z, v.w);
        uint2 pk; pk.x = *(unsigned*)&h0; pk.y = *(unsigned*)&h1;
        *(uint2*)&Bs[k * 64 + c4 * 4] = pk;
    }

    if (blockIdx.x == 0 && w < NREL) {
        float acc = 0.f;
        for (int hh = lane; hh < H; hh += 32) {
            float v = 0.f;
            #pragma unroll
            for (int r = 0; r < 16; r++) v += rel[w * 16 + r] * Wp[r * H + hh];
            acc += v * att[2 * H + hh];
        }
        #pragma unroll
        for (int o = 16; o; o >>= 1) acc += __shfl_xor_sync(0xffffffffu, acc, o);
        if (lane == 0) g_q[w] = acc;
    }

    cudaGridDependencySynchronize();   // g_h produced by predecessor

    for (int i = t; i < 128 * 16; i += 256) {
        int r = i >> 4, c4 = i & 15;
        int node = n0 + r;
        float4 v = make_float4(0.f, 0.f, 0.f, 0.f);
        if (node < N) v = *(const float4*)&g_h[node * H + c4 * 4];
        __half2 h0 = __floats2half2_rn(v.x, v.y);
        __half2 h1 = __floats2half2_rn(v.z, v.w);
        uint2 pk; pk.x = *(unsigned*)&h0; pk.y = *(unsigned*)&h1;
        *(uint2*)&As[r * LDA + c4 * 4] = pk;
    }
    __syncthreads();

    wmma::fragment<wmma::accumulator, 16, 16, 16, float> acc[4];
    #pragma unroll
    for (int nt = 0; nt < 4; nt++) wmma::fill_fragment(acc[nt], 0.f);
    #pragma unroll
    for (int ks = 0; ks < 4; ks++) {
        wmma::fragment<wmma::matrix_a, 16, 16, 16, __half, wmma::row_major> af;
        wmma::load_matrix_sync(af, As + (w * 16) * LDA + ks * 16, LDA);
        #pragma unroll
        for (int nt = 0; nt < 4; nt++) {
            wmma::fragment<wmma::matrix_b, 16, 16, 16, __half, wmma::row_major> bf;
            wmma::load_matrix_sync(bf, Bs + (ks * 16) * 64 + nt * 16, 64);
            wmma::mma_sync(acc[nt], af, bf, acc[nt]);
        }
    }
    __syncthreads();
    #pragma unroll
    for (int nt = 0; nt < 4; nt++)
        wmma::store_matrix_sync(Cs + (w * 16) * 64 + nt * 16, acc[nt], 64,
                                wmma::mem_row_major);
    __syncthreads();

    float ad0 = att[lane],      ad1 = att[lane + 32];
    float as0 = att[64 + lane], as1 = att[96 + lane];
    for (int rr = 0; rr < 16; rr++) {
        int r = w * 16 + rr;
        int node = n0 + r;
        float v0 = Cs[r * 64 + lane];
        float v1 = Cs[r * 64 + 32 + lane];
        float pd = v0 * ad0 + v1 * ad1;
        float ps = v0 * as0 + v1 * as1;
        #pragma unroll
        for (int o = 16; o; o >>= 1) {
            pd += __shfl_xor_sync(0xffffffffu, pd, o);
            ps += __shfl_xor_sync(0xffffffffu, ps, o);
        }
        float u0 = Cs[r * 64 + 2 * lane];
        float u1 = Cs[r * 64 + 2 * lane + 1];
        if (node < N) {
            g_hmh[node * (H / 2) + lane] = __floats2half2_rn(u0, u1);
            if (lane == 0) { g_pd[node] = pd; g_ps[node] = ps; }
        }
    }
}

// ---------------------------------------------------------------
// Counting sort of edges by dst
// ---------------------------------------------------------------
__global__ __launch_bounds__(256) void k_hist(const int* __restrict__ dst, int E)
{
    int i = blockIdx.x * blockDim.x + threadIdx.x;
    cudaGridDependencySynchronize();   // g_deg zeroed by predecessor
    if (i < E) atomicAdd(&g_deg[dst[i]], 1);
}

__global__ __launch_bounds__(1024) void k_scan1(int N)
{
    __shared__ int ws[32];
    int t = threadIdx.x, lane = t & 31, w = t >> 5;
    int i = blockIdx.x * 1024 + t;
    cudaGridDependencySynchronize();
    int v = (i < N) ? g_deg[i] : 0;
    #pragma unroll
    for (int o = 1; o < 32; o <<= 1) {
        int u = __shfl_up_sync(0xffffffffu, v, o);
        if (lane >= o) v += u;
    }
    if (lane == 31) ws[w] = v;
    __syncthreads();
    if (w == 0) {
        int bsum = ws[lane];
        #pragma unroll
        for (int o = 1; o < 32; o <<= 1) {
            int u = __shfl_up_sync(0xffffffffu, bsum, o);
            if (lane >= o) bsum += u;
        }
        ws[lane] = bsum;
    }
    __syncthreads();
    if (w) v += ws[w - 1];
    if (i < N) g_off[i + 1] = v;
    if (t == 1023) g_bsum[blockIdx.x] = v;
}

__global__ __launch_bounds__(1024) void k_scan23(int N, int nb)
{
    __shared__ int s[128];
    int t = threadIdx.x;
    cudaGridDependencySynchronize();
    if (t < 128) s[t] = (t < nb) ? g_bsum[t] : 0;
    __syncthreads();
    #pragma unroll
    for (int o = 1; o < 128; o <<= 1) {
        int v = (t >= o && t < 128) ? s[t - o] : 0;
        __syncthreads();
        if (t < 128) s[t] += v;
        __syncthreads();
    }
    int add = blockIdx.x ? s[blockIdx.x - 1] : 0;
    int i = blockIdx.x * 1024 + t;
    if (i < N) g_off[i + 1] += add;
    if (i == 0) g_off[0] = 0;
}

__global__ __launch_bounds__(256) void k_sortscatter(
    const int* __restrict__ src, const int* __restrict__ dst,
    const int* __restrict__ typ, const float* __restrict__ conf, int E)
{
    int i = blockIdx.x * blockDim.x + threadIdx.x;
    if (i >= E) return;
    // edge inputs are external; conf math can proceed pre-sync
    int t = min(max(typ[i], 0), NREL - 1);
    unsigned sv = (unsigned)src[i] | ((unsigned)t << 20);
    float cv = 0.1f * __logf(fmaxf(conf[i], 1e-6f));
    int d = dst[i];
    cudaGridDependencySynchronize();   // g_off/g_cur from scan chain
    int pos = g_off[d] + atomicAdd(&g_cur[d], 1);
    g_srcs[pos] = sv;
    g_dsts[pos] = d;
    g_cf[pos]   = cv;
}

// ---------------------------------------------------------------
// K_w: edge-parallel coalesced logit + exp, 2 edges per thread
// ---------------------------------------------------------------
__global__ __launch_bounds__(256) void k_w(int E)
{
    int i = (blockIdx.x * blockDim.x + threadIdx.x) * 2;
    cudaGridDependencySynchronize();   // pd/ps from msg, srcs/cf from sort
    if (i >= E) return;
    uint2  p2 = *(const uint2*)&g_srcs[i];
    int2   d2 = *(const int2*)&g_dsts[i];
    float2 c2 = *(const float2*)&g_cf[i];
    float e0 = g_pd[d2.x] + g_ps[p2.x & 0xFFFFF] + g_q[p2.x >> 20];
    e0 = e0 > 0.f ? e0 : 0.2f * e0;
    e0 += c2.x;
    float e1 = g_pd[d2.y] + g_ps[p2.y & 0xFFFFF] + g_q[p2.y >> 20];
    e1 = e1 > 0.f ? e1 : 0.2f * e1;
    e1 += c2.y;
    if (i + 1 < E) {
        *(float2*)&g_ex[i] = make_float2(__expf(e0), __expf(e1));
    } else {
        g_ex[i] = __expf(e0);
    }
}

// ---------------------------------------------------------------
// K_aggr: warp-per-node gather-sum (fp16 payload), software-pipelined
// metadata prefetch, fused softmax-normalize + residual + relu + LN.
// ---------------------------------------------------------------
__global__ __launch_bounds__(256) void k_aggr(
    const float* __restrict__ bias, const float* __restrict__ lng,
    const float* __restrict__ lnb, float* __restrict__ hout, int N)
{
    int n = (blockIdx.x * blockDim.x + threadIdx.x) >> 5;
    cudaGridDependencySynchronize();   // g_ex from k_w
    if (n >= N) return;
    int lane = threadIdx.x & 31;
    int half = lane >> 4;
    int l    = lane & 15;
    int beg = g_off[n], end = g_off[n + 1];
    float4 acc = make_float4(0.f, 0.f, 0.f, 0.f);
    float ssum = 0.f;

    int j = beg + half;
    unsigned p0 = 0, p1 = 0;
    float e0 = 0.f, e1 = 0.f;
    if (j < end)     { p0 = g_srcs[j];     e0 = g_ex[j]; }
    if (j + 2 < end) { p1 = g_srcs[j + 2]; e1 = g_ex[j + 2]; }
    for (; j + 2 < end; j += 4) {
        unsigned q0 = g_srcs[j + 4], q1 = g_srcs[j + 6];
        float f0 = g_ex[j + 4], f1 = g_ex[j + 6];
        uint2 r0 = *(const uint2*)&g_hmh[(p0 & 0xFFFFF) * (H/2) + l * 2];
        uint2 r1 = *(const uint2*)&g_hmh[(p1 & 0xFFFFF) * (H/2) + l * 2];
        float2 a0 = __half22float2(*(__half2*)&r0.x);
        float2 b0 = __half22float2(*(__half2*)&r0.y);
        float2 a1 = __half22float2(*(__half2*)&r1.x);
        float2 b1 = __half22float2(*(__half2*)&r1.y);
        acc.x += e0 * a0.x + e1 * a1.x;
        acc.y += e0 * a0.y + e1 * a1.y;
        acc.z += e0 * b0.x + e1 * b1.x;
        acc.w += e0 * b0.y + e1 * b1.y;
        ssum += e0 + e1;
        p0 = q0; p1 = q1; e0 = f0; e1 = f1;
    }
    if (j < end) {
        uint2 r = *(const uint2*)&g_hmh[(p0 & 0xFFFFF) * (H/2) + l * 2];
        float2 a = __half22float2(*(__half2*)&r.x);
        float2 b = __half22float2(*(__half2*)&r.y);
        acc.x += e0 * a.x; acc.y += e0 * a.y;
        acc.z += e0 * b.x; acc.w += e0 * b.y;
        ssum += e0;
    }

    acc.x += __shfl_xor_sync(0xffffffffu, acc.x, 16);
    acc.y += __shfl_xor_sync(0xffffffffu, acc.y, 16);
    acc.z += __shfl_xor_sync(0xffffffffu, acc.z, 16);
    acc.w += __shfl_xor_sync(0xffffffffu, acc.w, 16);
    ssum  += __shfl_xor_sync(0xffffffffu, ssum,  16);
    float inv = (ssum > 0.f) ? (1.f / ssum) : 0.f;
    float4 hv = *(const float4*)&g_h[n * H + l * 4];
    float4 bb = *(const float4*)&bias[l * 4];
    float4 u;
    u.x = hv.x + fmaxf(acc.x * inv + bb.x, 0.f);
    u.y = hv.y + fmaxf(acc.y * inv + bb.y, 0.f);
    u.z = hv.z + fmaxf(acc.z * inv + bb.z, 0.f);
    u.w = hv.w + fmaxf(acc.w * inv + bb.w, 0.f);
    float s = u.x + u.y + u.z + u.w;
    #pragma unroll
    for (int o = 16; o; o >>= 1) s += __shfl_xor_sync(0xffffffffu, s, o);
    float mu = s * (1.f / 128.f);
    float4 d4 = make_float4(u.x - mu, u.y - mu, u.z - mu, u.w - mu);
    float vs = d4.x*d4.x + d4.y*d4.y + d4.z*d4.z + d4.w*d4.w;
    #pragma unroll
    for (int o = 16; o; o >>= 1) vs += __shfl_xor_sync(0xffffffffu, vs, o);
    float invs = rsqrtf(vs * (1.f / 128.f) + 1e-5f);
    if (half == 0) {
        float4 g4 = *(const float4*)&lng[l * 4];
        float4 b2 = *(const float4*)&lnb[l * 4];
        float* outp = hout ? hout : g_h;
        float4 o4;
        o4.x = d4.x * invs * g4.x + b2.x;
        o4.y = d4.y * invs * g4.y + b2.y;
        o4.z = d4.z * invs * g4.z + b2.z;
        o4.w = d4.w * invs * g4.w + b2.w;
        *(float4*)&outp[n * H + l * 4] = o4;
    }
}

// ---------------------------------------------------------------
template <typename... Args>
static inline void launch_pdl(void (*kern)(Args...), dim3 grid, dim3 block,
                              Args... args)
{
    cudaLaunchConfig_t cfg = {};
    cfg.gridDim = grid;
    cfg.blockDim = block;
    cfg.stream = 0;
    cudaLaunchAttribute attr[1];
    attr[0].id = cudaLaunchAttributeProgrammaticStreamSerialization;
    attr[0].val.programmaticStreamSerializationAllowed = 1;
    cfg.attrs = attr;
    cfg.numAttrs = 1;
    cudaLaunchKernelEx(&cfg, kern, args...);
}

extern "C" void kernel_launch(void* const* d_in, const int* in_sizes, int n_in,
                              void* d_out, int out_size)
{
    const float* x         = (const float*)d_in[0];
    const float* W_in      = (const float*)d_in[1];
    const float* b_in      = (const float*)d_in[2];
    const float* W_msg     = (const float*)d_in[3];
    const float* rel_emb   = (const float*)d_in[4];
    const float* W_relproj = (const float*)d_in[5];
    const float* att_vec   = (const float*)d_in[6];
    const float* bias      = (const float*)d_in[7];
    const float* ln_g      = (const float*)d_in[8];
    const float* ln_b      = (const float*)d_in[9];
    const float* edge_attr = (const float*)d_in[10];
    const int*   edge_index= (const int*)d_in[11];
    const int*   edge_type = (const int*)d_in[12];
    float* out = (float*)d_out;

    int N = in_sizes[0] / INF;
    int E = in_sizes[12];
    int L = in_sizes[7] / H;
    const int* src = edge_index;
    const int* dst = edge_index + E;
    int nb = (N + 1023) / 1024;

    launch_pdl(k_input_mma, dim3((N + 127) / 128), dim3(256), x, W_in, b_in, N);

    launch_pdl(k_hist, dim3((E + 255) / 256), dim3(256), dst, E);
    launch_pdl(k_scan1, dim3(nb), dim3(1024), N);
    launch_pdl(k_scan23, dim3(nb), dim3(1024), N, nb);
    launch_pdl(k_sortscatter, dim3((E + 255) / 256), dim3(256),
               src, dst, edge_type, edge_attr, E);

    for (int l = 0; l < L; l++) {
        launch_pdl(k_msg_mma, dim3((N + 127) / 128), dim3(256),
                   (const float*)(W_msg + l * H * H),
                   (const float*)(att_vec + l * 3 * H),
                   (const float*)(rel_emb + l * NREL * 16),
                   (const float*)(W_relproj + l * 16 * H), N);
        launch_pdl(k_w, dim3((E / 2 + 255) / 256), dim3(256), E);
        launch_pdl(k_aggr, dim3((N * 32 + 255) / 256), dim3(256),
                   (const float*)(bias + l * H),
                   (const float*)(ln_g + l * H),
                   (const float*)(ln_b + l * H),
                   (l == L - 1) ? out : (float*)nullptr, N);
    }
}

// round 17
// speedup vs baseline: 1.1373x; 1.0471x over previous
#include <cuda_runtime.h>
#include <cuda_fp16.h>
#include <mma.h>

using namespace nvcuda;

#define H      64
#define INF    128
#define NREL   8
#define NMAX   100000
#define EMAX   1600000

// ---- scratch ----
__device__ __align__(128) float   g_h  [NMAX * H];
__device__ __align__(128) __half2 g_hmh[NMAX * (H / 2)];  // hm in fp16 (gather payload)
__device__ __align__(128) float g_ps [NMAX];
__device__ __align__(128) float g_pd [NMAX];
__device__ __align__(128) float g_q  [NREL];
__device__ __align__(128) unsigned g_srcs[EMAX + 8];   // src | (typ<<20), dst-sorted
__device__ __align__(128) int      g_dsts[EMAX];
__device__ __align__(128) float    g_cf  [EMAX];
__device__ __align__(128) float    g_ex  [EMAX + 8];   // exp(e) (+pad for prefetch)
__device__ __align__(128) int g_deg [NMAX];
__device__ __align__(128) int g_cur [NMAX];
__device__ __align__(128) int g_off [NMAX + 1];
__device__ __align__(128) int g_bsum[128];

#define LDA 72   // fp16 leading dim for A tiles (pad vs 64 to break conflicts)

// ---------------------------------------------------------------
// K0 (WMMA): combined kernel.
//   blocks [0, IB):      h = relu(x @ W_in + b_in)
//   blocks [IB, IB+HB):  edge-degree histogram (g_deg pre-zeroed by memset)
// No barrier couples the two roles — true SM-level concurrency.
// ---------------------------------------------------------------
__global__ __launch_bounds__(256) void k_input_mma(
    const float* __restrict__ x, const float* __restrict__ W,
    const float* __restrict__ b, const int* __restrict__ dst,
    int N, int E, int IB, int HB)
{
    __shared__ __align__(128) char sm[32768];
    __half* As = (__half*)sm;               // [128][LDA]
    __half* Bs = (__half*)(sm + 18432);     // [64][64] row-major (k,n)
    float*  Cs = (float*)sm;                // [128][64]

    int t = threadIdx.x, w = t >> 5;

    cudaGridDependencySynchronize();        // memset(g_deg/g_cur) predecessors

    if (blockIdx.x >= IB) {
        // histogram role
        for (int i = (blockIdx.x - IB) * 256 + t; i < E; i += HB * 256)
            atomicAdd(&g_deg[dst[i]], 1);
        return;
    }

    int n0 = blockIdx.x * 128;

    wmma::fragment<wmma::accumulator, 16, 16, 16, float> acc[4];
    #pragma unroll
    for (int nt = 0; nt < 4; nt++) wmma::fill_fragment(acc[nt], 0.f);

    for (int p = 0; p < 2; p++) {
        __syncthreads();
        for (int i = t; i < 128 * 16; i += 256) {
            int r = i >> 4, c4 = i & 15;
            int node = n0 + r;
            float4 v = make_float4(0.f, 0.f, 0.f, 0.f);
            if (node < N) v = *(const float4*)&x[node * INF + p * 64 + c4 * 4];
            __half2 h0 = __floats2half2_rn(v.x, v.y);
            __half2 h1 = __floats2half2_rn(v.z, v.w);
            uint2 pk; pk.x = *(unsigned*)&h0; pk.y = *(unsigned*)&h1;
            *(uint2*)&As[r * LDA + c4 * 4] = pk;
        }
        for (int i = t; i < 64 * 16; i += 256) {
            int k = i >> 4, c4 = i & 15;
            float4 v = *(const float4*)&W[(p * 64 + k) * 64 + c4 * 4];
            __half2 h0 = __floats2half2_rn(v.x, v.y);
            __half2 h1 = __floats2half2_rn(v.z, v.w);
            uint2 pk; pk.x = *(unsigned*)&h0; pk.y = *(unsigned*)&h1;
            *(uint2*)&Bs[k * 64 + c4 * 4] = pk;
        }
        __syncthreads();
        #pragma unroll
        for (int ks = 0; ks < 4; ks++) {
            wmma::fragment<wmma::matrix_a, 16, 16, 16, __half, wmma::row_major> af;
            wmma::load_matrix_sync(af, As + (w * 16) * LDA + ks * 16, LDA);
            #pragma unroll
            for (int nt = 0; nt < 4; nt++) {
                wmma::fragment<wmma::matrix_b, 16, 16, 16, __half, wmma::row_major> bf;
                wmma::load_matrix_sync(bf, Bs + (ks * 16) * 64 + nt * 16, 64);
                wmma::mma_sync(acc[nt], af, bf, acc[nt]);
            }
        }
    }
    __syncthreads();
    #pragma unroll
    for (int nt = 0; nt < 4; nt++)
        wmma::store_matrix_sync(Cs + (w * 16) * 64 + nt * 16, acc[nt], 64,
                                wmma::mem_row_major);
    __syncthreads();
    for (int i = t; i < 128 * 16; i += 256) {
        int r = i >> 4, c4 = i & 15;
        int node = n0 + r;
        if (node < N) {
            float4 v = *(float4*)&Cs[r * 64 + c4 * 4];
            float4 bb = *(const float4*)&b[c4 * 4];
            float4 o;
            o.x = fmaxf(v.x + bb.x, 0.f);
            o.y = fmaxf(v.y + bb.y, 0.f);
            o.z = fmaxf(v.z + bb.z, 0.f);
            o.w = fmaxf(v.w + bb.w, 0.f);
            *(float4*)&g_h[node * H + c4 * 4] = o;
        }
    }
}

// ---------------------------------------------------------------
// K1 (WMMA): hm = h @ W_msg (fp16 out) + fused pd/ps + fused q (block 0).
// ---------------------------------------------------------------
__global__ __launch_bounds__(256) void k_msg_mma(
    const float* __restrict__ Wm, const float* __restrict__ att,
    const float* __restrict__ rel, const float* __restrict__ Wp, int N)
{
    __shared__ __align__(128) char sm[32768];
    __half* As = (__half*)sm;               // [128][LDA]
    __half* Bs = (__half*)(sm + 18432);     // [64][64]
    float*  Cs = (float*)sm;                // [128][64]

    int t = threadIdx.x, w = t >> 5, lane = t & 31;
    int n0 = blockIdx.x * 128;

    // weights/att are kernel inputs (not predecessor-written): stage B early
    for (int i = t; i < 64 * 16; i += 256) {
        int k = i >> 4, c4 = i & 15;
        float4 v = *(const float4*)&Wm[k * 64 + c4 * 4];
        __half2 h0 = __floats2half2_rn(v.x, v.y);
        __half2 h1 = __floats2half2_rn(v.z, v.w);
        uint2 pk; pk.x = *(unsigned*)&h0; pk.y = *(unsigned*)&h1;
        *(uint2*)&Bs[k * 64 + c4 * 4] = pk;
    }

    if (blockIdx.x == 0 && w < NREL) {
        float acc = 0.f;
        for (int hh = lane; hh < H; hh += 32) {
            float v = 0.f;
            #pragma unroll
            for (int r = 0; r < 16; r++) v += rel[w * 16 + r] * Wp[r * H + hh];
            acc += v * att[2 * H + hh];
        }
        #pragma unroll
        for (int o = 16; o; o >>= 1) acc += __shfl_xor_sync(0xffffffffu, acc, o);
        if (lane == 0) g_q[w] = acc;
    }

    cudaGridDependencySynchronize();   // g_h produced by predecessor

    for (int i = t; i < 128 * 16; i += 256) {
        int r = i >> 4, c4 = i & 15;
        int node = n0 + r;
        float4 v = make_float4(0.f, 0.f, 0.f, 0.f);
        if (node < N) v = *(const float4*)&g_h[node * H + c4 * 4];
        __half2 h0 = __floats2half2_rn(v.x, v.y);
        __half2 h1 = __floats2half2_rn(v.z, v.w);
        uint2 pk; pk.x = *(unsigned*)&h0; pk.y = *(unsigned*)&h1;
        *(uint2*)&As[r * LDA + c4 * 4] = pk;
    }
    __syncthreads();

    wmma::fragment<wmma::accumulator, 16, 16, 16, float> acc[4];
    #pragma unroll
    for (int nt = 0; nt < 4; nt++) wmma::fill_fragment(acc[nt], 0.f);
    #pragma unroll
    for (int ks = 0; ks < 4; ks++) {
        wmma::fragment<wmma::matrix_a, 16, 16, 16, __half, wmma::row_major> af;
        wmma::load_matrix_sync(af, As + (w * 16) * LDA + ks * 16, LDA);
        #pragma unroll
        for (int nt = 0; nt < 4; nt++) {
            wmma::fragment<wmma::matrix_b, 16, 16, 16, __half, wmma::row_major> bf;
            wmma::load_matrix_sync(bf, Bs + (ks * 16) * 64 + nt * 16, 64);
            wmma::mma_sync(acc[nt], af, bf, acc[nt]);
        }
    }
    __syncthreads();
    #pragma unroll
    for (int nt = 0; nt < 4; nt++)
        wmma::store_matrix_sync(Cs + (w * 16) * 64 + nt * 16, acc[nt], 64,
                                wmma::mem_row_major);
    __syncthreads();

    float ad0 = att[lane],      ad1 = att[lane + 32];
    float as0 = att[64 + lane], as1 = att[96 + lane];
    for (int rr = 0; rr < 16; rr++) {
        int r = w * 16 + rr;
        int node = n0 + r;
        float v0 = Cs[r * 64 + lane];
        float v1 = Cs[r * 64 + 32 + lane];
        float pd = v0 * ad0 + v1 * ad1;
        float ps = v0 * as0 + v1 * as1;
        #pragma unroll
        for (int o = 16; o; o >>= 1) {
            pd += __shfl_xor_sync(0xffffffffu, pd, o);
            ps += __shfl_xor_sync(0xffffffffu, ps, o);
        }
        float u0 = Cs[r * 64 + 2 * lane];
        float u1 = Cs[r * 64 + 2 * lane + 1];
        if (node < N) {
            g_hmh[node * (H / 2) + lane] = __floats2half2_rn(u0, u1);
            if (lane == 0) { g_pd[node] = pd; g_ps[node] = ps; }
        }
    }
}

// ---------------------------------------------------------------
// Prefix-sum of degrees
// ---------------------------------------------------------------
__global__ __launch_bounds__(1024) void k_scan1(int N)
{
    __shared__ int ws[32];
    int t = threadIdx.x, lane = t & 31, w = t >> 5;
    int i = blockIdx.x * 1024 + t;
    cudaGridDependencySynchronize();
    int v = (i < N) ? g_deg[i] : 0;
    #pragma unroll
    for (int o = 1; o < 32; o <<= 1) {
        int u = __shfl_up_sync(0xffffffffu, v, o);
        if (lane >= o) v += u;
    }
    if (lane == 31) ws[w] = v;
    __syncthreads();
    if (w == 0) {
        int bsum = ws[lane];
        #pragma unroll
        for (int o = 1; o < 32; o <<= 1) {
            int u = __shfl_up_sync(0xffffffffu, bsum, o);
            if (lane >= o) bsum += u;
        }
        ws[lane] = bsum;
    }
    __syncthreads();
    if (w) v += ws[w - 1];
    if (i < N) g_off[i + 1] = v;
    if (t == 1023) g_bsum[blockIdx.x] = v;
}

__global__ __launch_bounds__(1024) void k_scan23(int N, int nb)
{
    __shared__ int s[128];
    int t = threadIdx.x;
    cudaGridDependencySynchronize();
    if (t < 128) s[t] = (t < nb) ? g_bsum[t] : 0;
    __syncthreads();
    #pragma unroll
    for (int o = 1; o < 128; o <<= 1) {
        int v = (t >= o && t < 128) ? s[t - o] : 0;
        __syncthreads();
        if (t < 128) s[t] += v;
        __syncthreads();
    }
    int add = blockIdx.x ? s[blockIdx.x - 1] : 0;
    int i = blockIdx.x * 1024 + t;
    if (i < N) g_off[i + 1] += add;
    if (i == 0) g_off[0] = 0;
}

__global__ __launch_bounds__(256) void k_sortscatter(
    const int* __restrict__ src, const int* __restrict__ dst,
    const int* __restrict__ typ, const float* __restrict__ conf, int E)
{
    int i = blockIdx.x * blockDim.x + threadIdx.x;
    if (i >= E) return;
    int t = min(max(typ[i], 0), NREL - 1);
    unsigned sv = (unsigned)src[i] | ((unsigned)t << 20);
    float cv = 0.1f * __logf(fmaxf(conf[i], 1e-6f));
    int d = dst[i];
    cudaGridDependencySynchronize();   // g_off/g_cur from scan chain
    int pos = g_off[d] + atomicAdd(&g_cur[d], 1);
    g_srcs[pos] = sv;
    g_dsts[pos] = d;
    g_cf[pos]   = cv;
}

// ---------------------------------------------------------------
// K_w: edge-parallel coalesced logit + exp, 2 edges per thread
// ---------------------------------------------------------------
__global__ __launch_bounds__(256) void k_w(int E)
{
    int i = (blockIdx.x * blockDim.x + threadIdx.x) * 2;
    cudaGridDependencySynchronize();
    if (i >= E) return;
    uint2  p2 = *(const uint2*)&g_srcs[i];
    int2   d2 = *(const int2*)&g_dsts[i];
    float2 c2 = *(const float2*)&g_cf[i];
    float e0 = g_pd[d2.x] + g_ps[p2.x & 0xFFFFF] + g_q[p2.x >> 20];
    e0 = e0 > 0.f ? e0 : 0.2f * e0;
    e0 += c2.x;
    float e1 = g_pd[d2.y] + g_ps[p2.y & 0xFFFFF] + g_q[p2.y >> 20];
    e1 = e1 > 0.f ? e1 : 0.2f * e1;
    e1 += c2.y;
    if (i + 1 < E) {
        *(float2*)&g_ex[i] = make_float2(__expf(e0), __expf(e1));
    } else {
        g_ex[i] = __expf(e0);
    }
}

// ---------------------------------------------------------------
// K_aggr: warp-per-node gather-sum (fp16 payload), software-pipelined
// metadata prefetch, fused softmax-normalize + residual + relu + LN.
// ---------------------------------------------------------------
__global__ __launch_bounds__(256) void k_aggr(
    const float* __restrict__ bias, const float* __restrict__ lng,
    const float* __restrict__ lnb, float* __restrict__ hout, int N)
{
    int n = (blockIdx.x * blockDim.x + threadIdx.x) >> 5;
    cudaGridDependencySynchronize();
    if (n >= N) return;
    int lane = threadIdx.x & 31;
    int half = lane >> 4;
    int l    = lane & 15;
    int beg = g_off[n], end = g_off[n + 1];
    float4 acc = make_float4(0.f, 0.f, 0.f, 0.f);
    float ssum = 0.f;

    int j = beg + half;
    unsigned p0 = 0, p1 = 0;
    float e0 = 0.f, e1 = 0.f;
    if (j < end)     { p0 = g_srcs[j];     e0 = g_ex[j]; }
    if (j + 2 < end) { p1 = g_srcs[j + 2]; e1 = g_ex[j + 2]; }
    for (; j + 2 < end; j += 4) {
        unsigned q0 = g_srcs[j + 4], q1 = g_srcs[j + 6];
        float f0 = g_ex[j + 4], f1 = g_ex[j + 6];
        uint2 r0 = *(const uint2*)&g_hmh[(p0 & 0xFFFFF) * (H/2) + l * 2];
        uint2 r1 = *(const uint2*)&g_hmh[(p1 & 0xFFFFF) * (H/2) + l * 2];
        float2 a0 = __half22float2(*(__half2*)&r0.x);
        float2 b0 = __half22float2(*(__half2*)&r0.y);
        float2 a1 = __half22float2(*(__half2*)&r1.x);
        float2 b1 = __half22float2(*(__half2*)&r1.y);
        acc.x += e0 * a0.x + e1 * a1.x;
        acc.y += e0 * a0.y + e1 * a1.y;
        acc.z += e0 * b0.x + e1 * b1.x;
        acc.w += e0 * b0.y + e1 * b1.y;
        ssum += e0 + e1;
        p0 = q0; p1 = q1; e0 = f0; e1 = f1;
    }
    if (j < end) {
        uint2 r = *(const uint2*)&g_hmh[(p0 & 0xFFFFF) * (H/2) + l * 2];
        float2 a = __half22float2(*(__half2*)&r.x);
        float2 b = __half22float2(*(__half2*)&r.y);
        acc.x += e0 * a.x; acc.y += e0 * a.y;
        acc.z += e0 * b.x; acc.w += e0 * b.y;
        ssum += e0;
    }

    acc.x += __shfl_xor_sync(0xffffffffu, acc.x, 16);
    acc.y += __shfl_xor_sync(0xffffffffu, acc.y, 16);
    acc.z += __shfl_xor_sync(0xffffffffu, acc.z, 16);
    acc.w += __shfl_xor_sync(0xffffffffu, acc.w, 16);
    ssum  += __shfl_xor_sync(0xffffffffu, ssum,  16);
    float inv = (ssum > 0.f) ? (1.f / ssum) : 0.f;
    float4 hv = *(const float4*)&g_h[n * H + l * 4];
    float4 bb = *(const float4*)&bias[l * 4];
    float4 u;
    u.x = hv.x + fmaxf(acc.x * inv + bb.x, 0.f);
    u.y = hv.y + fmaxf(acc.y * inv + bb.y, 0.f);
    u.z = hv.z + fmaxf(acc.z * inv + bb.z, 0.f);
    u.w = hv.w + fmaxf(acc.w * inv + bb.w, 0.f);
    float s = u.x + u.y + u.z + u.w;
    #pragma unroll
    for (int o = 16; o; o >>= 1) s += __shfl_xor_sync(0xffffffffu, s, o);
    float mu = s * (1.f / 128.f);
    float4 d4 = make_float4(u.x - mu, u.y - mu, u.z - mu, u.w - mu);
    float vs = d4.x*d4.x + d4.y*d4.y + d4.z*d4.z + d4.w*d4.w;
    #pragma unroll
    for (int o = 16; o; o >>= 1) vs += __shfl_xor_sync(0xffffffffu, vs, o);
    float invs = rsqrtf(vs * (1.f / 128.f) + 1e-5f);
    if (half == 0) {
        float4 g4 = *(const float4*)&lng[l * 4];
        float4 b2 = *(const float4*)&lnb[l * 4];
        float* outp = hout ? hout : g_h;
        float4 o4;
        o4.x = d4.x * invs * g4.x + b2.x;
        o4.y = d4.y * invs * g4.y + b2.y;
        o4.z = d4.z * invs * g4.z + b2.z;
        o4.w = d4.w * invs * g4.w + b2.w;
        *(float4*)&outp[n * H + l * 4] = o4;
    }
}

// ---------------------------------------------------------------
template <typename... Args>
static inline void launch_pdl(void (*kern)(Args...), dim3 grid, dim3 block,
                              Args... args)
{
    cudaLaunchConfig_t cfg = {};
    cfg.gridDim = grid;
    cfg.blockDim = block;
    cfg.stream = 0;
    cudaLaunchAttribute attr[1];
    attr[0].id = cudaLaunchAttributeProgrammaticStreamSerialization;
    attr[0].val.programmaticStreamSerializationAllowed = 1;
    cfg.attrs = attr;
    cfg.numAttrs = 1;
    cudaLaunchKernelEx(&cfg, kern, args...);
}

extern "C" void kernel_launch(void* const* d_in, const int* in_sizes, int n_in,
                              void* d_out, int out_size)
{
    const float* x         = (const float*)d_in[0];
    const float* W_in      = (const float*)d_in[1];
    const float* b_in      = (const float*)d_in[2];
    const float* W_msg     = (const float*)d_in[3];
    const float* rel_emb   = (const float*)d_in[4];
    const float* W_relproj = (const float*)d_in[5];
    const float* att_vec   = (const float*)d_in[6];
    const float* bias      = (const float*)d_in[7];
    const float* ln_g      = (const float*)d_in[8];
    const float* ln_b      = (const float*)d_in[9];
    const float* edge_attr = (const float*)d_in[10];
    const int*   edge_index= (const int*)d_in[11];
    const int*   edge_type = (const int*)d_in[12];
    float* out = (float*)d_out;

    int N = in_sizes[0] / INF;
    int E = in_sizes[12];
    int L = in_sizes[7] / H;
    const int* src = edge_index;
    const int* dst = edge_index + E;
    int nb = (N + 1023) / 1024;

    void *deg_p = nullptr, *cur_p = nullptr;
    cudaGetSymbolAddress(&deg_p, g_deg);
    cudaGetSymbolAddress(&cur_p, g_cur);
    cudaMemsetAsync(deg_p, 0, N * sizeof(int));
    cudaMemsetAsync(cur_p, 0, N * sizeof(int));

    int IB = (N + 127) / 128;          // input-GEMM blocks
    int HB = (E + 255) / 256;          // histogram blocks (thread-per-edge)
    launch_pdl(k_input_mma, dim3(IB + HB), dim3(256),
               x, W_in, b_in, dst, N, E, IB, HB);

    launch_pdl(k_scan1, dim3(nb), dim3(1024), N);
    launch_pdl(k_scan23, dim3(nb), dim3(1024), N, nb);
    launch_pdl(k_sortscatter, dim3((E + 255) / 256), dim3(256),
               src, dst, edge_type, edge_attr, E);

    for (int l = 0; l < L; l++) {
        launch_pdl(k_msg_mma, dim3((N + 127) / 128), dim3(256),
                   (const float*)(W_msg + l * H * H),
                   (const float*)(att_vec + l * 3 * H),
                   (const float*)(rel_emb + l * NREL * 16),
                   (const float*)(W_relproj + l * 16 * H), N);
        launch_pdl(k_w, dim3((E / 2 + 255) / 256), dim3(256), E);
        launch_pdl(k_aggr, dim3((N * 32 + 255) / 256), dim3(256),
                   (const float*)(bias + l * H),
                   (const float*)(ln_g + l * H),
                   (const float*)(ln_b + l * H),
                   (l == L - 1) ? out : (float*)nullptr, N);
    }
}